// round 13
// baseline (speedup 1.0000x reference)
#include <cuda_runtime.h>
#include <cuda_bf16.h>
#include <cuda_fp16.h>
#include <cstdint>

#define BB 32
#define SS 2048
#define HH 1024

// scores kernel geometry (fp16 operands)
#define MT 64               // CTA M (keys rows)  -> grid 1024 = ~7 full waves
#define NTILE 256           // CTA N per pass
#define NPASS (HH / NTILE)  // 4
#define KC 64               // K halves per chunk (128B per row)
#define CPP (HH / KC)       // chunks per pass = 16
#define NCHUNKS (NPASS * CPP)  // 64
#define NSTG 4

#define STG_BYTES (8192 + 32768)    // A 8KB + B 32KB = 40KB
#define A_OFF(s)  ((s) * STG_BYTES)
#define B_OFF(s)  ((s) * STG_BYTES + 8192)
#define PRE_OFF   (NSTG * STG_BYTES)        // 163840
#define VA_OFF    (PRE_OFF + 4096)
#define RED_OFF   (VA_OFF + 4096)
#define SMEM_BYTES (RED_OFF + 1280)         // ~173KB

// ---------- device scratch ----------
__device__ float g_pre[BB * HH];
__device__ float g_scores[BB * SS];
__device__ float g_part[32 * BB * HH];
__device__ __align__(16) __half g_keys_h[(size_t)BB * SS * HH];  // 128 MB
__device__ __align__(16) __half g_ua_h[HH * HH];                 // 2 MB

// ---------- helpers ----------
__device__ __forceinline__ void cp16(void* dst_smem, const void* src) {
    uint32_t d;
    asm("{ .reg .u64 t; cvta.to.shared.u64 t, %1; cvt.u32.u64 %0, t; }" : "=r"(d) : "l"(dst_smem));
    asm volatile("cp.async.cg.shared.global [%0], [%1], 16;" :: "r"(d), "l"(src) : "memory");
}
#define CP_COMMIT() asm volatile("cp.async.commit_group;" ::: "memory")
template <int N> __device__ __forceinline__ void cp_wait() {
    asm volatile("cp.async.wait_group %0;" :: "n"(N) : "memory");
}
#define LDSM_X4(r0, r1, r2, r3, addr) \
    asm volatile("ldmatrix.sync.aligned.m8n8.x4.shared.b16 {%0,%1,%2,%3}, [%4];" \
        : "=r"(r0), "=r"(r1), "=r"(r2), "=r"(r3) : "r"(addr))
#define MMA_F16(c, a, b0, b1) \
    asm volatile("mma.sync.aligned.m16n8k16.row.col.f32.f16.f16.f32 " \
        "{%0,%1,%2,%3}, {%4,%5,%6,%7}, {%8,%9}, {%0,%1,%2,%3};" \
        : "+f"((c)[0]), "+f"((c)[1]), "+f"((c)[2]), "+f"((c)[3]) \
        : "r"((a)[0]), "r"((a)[1]), "r"((a)[2]), "r"((a)[3]), "r"(b0), "r"(b1))

__device__ __forceinline__ float ftanh(float x) {
    float e = __expf(2.0f * x);
    return 1.0f - __fdividef(2.0f, e + 1.0f);
}

// ---------------------------------------------------------------------------
// K0: f32 -> fp16 conversion (8 floats / thread, vectorized)
// ---------------------------------------------------------------------------
__global__ void cvt_kernel(const float4* __restrict__ src, __half2* __restrict__ dst) {
    size_t i = (size_t)blockIdx.x * blockDim.x + threadIdx.x;
    float4 a = src[2 * i];
    float4 b = src[2 * i + 1];
    dst[4 * i + 0] = __floats2half2_rn(a.x, a.y);
    dst[4 * i + 1] = __floats2half2_rn(a.z, a.w);
    dst[4 * i + 2] = __floats2half2_rn(b.x, b.y);
    dst[4 * i + 3] = __floats2half2_rn(b.z, b.w);
}

// ---------------------------------------------------------------------------
// K1: pre[b,k] = query[b]·Wa_w[k] + Wa_b[k] + Ua_b[k]  (fp32, accuracy anchor)
// ---------------------------------------------------------------------------
__global__ void qproj_kernel(const float* __restrict__ query,
                             const float* __restrict__ Wa_w,
                             const float* __restrict__ Wa_b,
                             const float* __restrict__ Ua_b) {
    int gw = blockIdx.x * 8 + (threadIdx.x >> 5);
    int lane = threadIdx.x & 31;
    int b = gw >> 10;
    int k = gw & (HH - 1);
    const float* q = query + b * HH;
    const float* w = Wa_w + (size_t)k * HH;
    float sum = 0.f;
#pragma unroll 8
    for (int h = lane; h < HH; h += 32) sum += q[h] * w[h];
#pragma unroll
    for (int off = 16; off; off >>= 1) sum += __shfl_xor_sync(0xffffffffu, sum, off);
    if (lane == 0) g_pre[b * HH + k] = sum + Wa_b[k] + Ua_b[k];
}

// ---------------------------------------------------------------------------
// K2: fused scores via mma.sync m16n8k16 fp16 (fp32 accum).
// CTA 64(M) x 256(N) per pass, 4 passes; 16 warps (4M x 4N; warp tile 16x64).
// K streamed in 64-half chunks through a flat 4-stage cp.async ring.
// grid = (S/64, B) = 1024 CTAs (~7 full waves), block = 512.
// ---------------------------------------------------------------------------
__global__ __launch_bounds__(512, 1) void scores_kernel(const float* __restrict__ Va_w) {
    extern __shared__ char smem[];
    float* pre_s = (float*)(smem + PRE_OFF);
    float* va_s  = (float*)(smem + VA_OFF);
    float* red   = (float*)(smem + RED_OFF);   // [4][64]

    const int tid = threadIdx.x;
    const int wid = tid >> 5;
    const int lane = tid & 31;
    const int g = lane >> 2;
    const int tg = lane & 3;
    const int wm = wid & 3;        // warp M index 0..3 (16 rows each)
    const int wn = wid >> 2;       // warp N index 0..3 (64 cols each)
    const int b = blockIdx.y;
    const int s0 = blockIdx.x * MT;

    uint32_t sb32;
    asm("{ .reg .u64 t; cvta.to.shared.u64 t, %1; cvt.u32.u64 %0, t; }"
        : "=r"(sb32) : "l"(smem));

    const char* gA = (const char*)(g_keys_h + ((size_t)b * SS + s0) * HH);

#pragma unroll
    for (int i = tid; i < HH; i += 512) {
        pre_s[i] = g_pre[b * HH + i];
        va_s[i]  = Va_w[i];
    }

    // ldmatrix lane invariants (swizzle term reduces to (lane&7)<<4)
    const uint32_t xr = (uint32_t)(lane & 7) << 4;
    const int a_row   = wm * 16 + ((lane >> 3) & 1) * 8 + (lane & 7);
    const uint32_t a_koff = (uint32_t)(lane >> 4) * 16;
    const int b_nrow  = wn * 64 + ((lane >> 4) << 3) + (lane & 7);     // + np*16
    const uint32_t b_koff = (uint32_t)((lane >> 3) & 1) * 16;

    // chunk loader: flat chunk cl -> stage cl&3, kbyte=(cl%CPP)*128, nt=cl/CPP
    auto load_chunk = [&](int cl) {
        int st = cl & 3;
        size_t kbyte = (size_t)(cl & (CPP - 1)) * 128;
        char* Ab = smem + A_OFF(st);
        char* Bb = smem + B_OFF(st);
        const char* gBp = (const char*)(g_ua_h + ((size_t)(cl >> 4) * NTILE) * HH);
        {   // A: 64 rows x 128B, 8 threads per row
            int m = tid >> 3, j = tid & 7;
            uint32_t sw = (uint32_t)(j * 16) ^ ((uint32_t)(m & 7) << 4);
            cp16(Ab + m * 128 + sw, gA + (size_t)m * (HH * 2) + kbyte + j * 16);
        }
#pragma unroll
        for (int r = 0; r < 4; r++) {   // B: 256 rows x 128B
            int id = tid + 512 * r;
            int m = id >> 3, j = id & 7;
            uint32_t sw = (uint32_t)(j * 16) ^ ((uint32_t)(m & 7) << 4);
            cp16(Bb + m * 128 + sw, gBp + (size_t)m * (HH * 2) + kbyte + j * 16);
        }
    };

    float sacc[2] = {0.f, 0.f};    // rows g and g+8 of this warp's 16
    float acc[8][4];
#pragma unroll
    for (int ni = 0; ni < 8; ni++)
#pragma unroll
        for (int q = 0; q < 4; q++) acc[ni][q] = 0.f;

    load_chunk(0); CP_COMMIT();
    load_chunk(1); CP_COMMIT();
    load_chunk(2); CP_COMMIT();

    for (int cc = 0; cc < NCHUNKS; cc++) {
        cp_wait<2>();
        __syncthreads();                       // chunk cc visible; stage (cc-1)&3 free
        if (cc + 3 < NCHUNKS) load_chunk(cc + 3);
        CP_COMMIT();                           // uniform group accounting

        uint32_t Ab32 = sb32 + A_OFF(cc & 3);
        uint32_t Bb32 = sb32 + B_OFF(cc & 3);
#pragma unroll
        for (int s = 0; s < 4; s++) {          // 4 k-steps of 16 halves
            uint32_t a[4];
            {
                uint32_t addr = Ab32 + (uint32_t)a_row * 128
                              + (((uint32_t)s * 32 + a_koff) ^ xr);
                LDSM_X4(a[0], a[1], a[2], a[3], addr);
            }
#pragma unroll
            for (int np = 0; np < 4; np++) {   // pairs of n8 tiles (16 n each)
                uint32_t bf[4];
                uint32_t addr = Bb32 + (uint32_t)(b_nrow + np * 16) * 128
                              + (((uint32_t)s * 32 + b_koff) ^ xr);
                LDSM_X4(bf[0], bf[1], bf[2], bf[3], addr);
                MMA_F16(acc[np * 2],     a, bf[0], bf[1]);
                MMA_F16(acc[np * 2 + 1], a, bf[2], bf[3]);
            }
        }

        if ((cc & (CPP - 1)) == CPP - 1) {
            // end of an n-pass: tanh + Va reduce, reset accumulators
            int nt = cc >> 4;
#pragma unroll
            for (int ni = 0; ni < 8; ni++) {
                int col0 = nt * NTILE + wn * 64 + ni * 8 + tg * 2;
                float p0 = pre_s[col0], p1 = pre_s[col0 + 1];
                float v0 = va_s[col0],  v1 = va_s[col0 + 1];
                sacc[0] += ftanh(acc[ni][0] + p0) * v0
                         + ftanh(acc[ni][1] + p1) * v1;
                sacc[1] += ftanh(acc[ni][2] + p0) * v0
                         + ftanh(acc[ni][3] + p1) * v1;
                acc[ni][0] = 0.f; acc[ni][1] = 0.f;
                acc[ni][2] = 0.f; acc[ni][3] = 0.f;
            }
        }
    }

    // quad reduce (lanes sharing a row), then across the 4 N-warps via smem
#pragma unroll
    for (int h = 0; h < 2; h++) {
        float v = sacc[h];
        v += __shfl_xor_sync(0xffffffffu, v, 1);
        v += __shfl_xor_sync(0xffffffffu, v, 2);
        if (tg == 0) red[wn * 64 + wm * 16 + h * 8 + g] = v;
    }
    __syncthreads();
    if (tid < 64)
        g_scores[b * SS + s0 + tid] =
            red[tid] + red[64 + tid] + red[128 + tid] + red[192 + tid];
}

// ---------------------------------------------------------------------------
// K3: softmax over S per batch (Va_b dropped: shift-invariant).
// ---------------------------------------------------------------------------
__global__ void softmax_kernel(float* __restrict__ out_w) {
    int b = blockIdx.x;
    int tid = threadIdx.x;
    __shared__ float red[256];
    float v[8];
    float mx = -1e30f;
#pragma unroll
    for (int j = 0; j < 8; j++) {
        v[j] = g_scores[b * SS + tid + 256 * j];
        mx = fmaxf(mx, v[j]);
    }
    red[tid] = mx;
    __syncthreads();
    for (int off = 128; off; off >>= 1) {
        if (tid < off) red[tid] = fmaxf(red[tid], red[tid + off]);
        __syncthreads();
    }
    mx = red[0];
    __syncthreads();
    float sum = 0.f;
#pragma unroll
    for (int j = 0; j < 8; j++) {
        v[j] = __expf(v[j] - mx);
        sum += v[j];
    }
    red[tid] = sum;
    __syncthreads();
    for (int off = 128; off; off >>= 1) {
        if (tid < off) red[tid] += red[tid + off];
        __syncthreads();
    }
    float inv = 1.f / red[0];
#pragma unroll
    for (int j = 0; j < 8; j++) out_w[b * SS + tid + 256 * j] = v[j] * inv;
}

// ---------------------------------------------------------------------------
// K4a: context partials over 32 S-chunks of 64 (deterministic, f32 keys)
// ---------------------------------------------------------------------------
__global__ void context_part_kernel(const float* __restrict__ keys,
                                    const float* __restrict__ w) {
    int b = blockIdx.x;
    int cy = blockIdx.y;
    int s0 = cy * 64;
    int t = threadIdx.x;
    __shared__ float ws[64];
    if (t < 64) ws[t] = w[b * SS + s0 + t];
    __syncthreads();
    const float4* kb = (const float4*)(keys + ((size_t)b * SS + s0) * HH);
    float4 acc = {0.f, 0.f, 0.f, 0.f};
    for (int s = 0; s < 64; s += 4) {
#pragma unroll
        for (int u = 0; u < 4; u++) {
            float wv = ws[s + u];
            float4 kv = kb[(size_t)(s + u) * (HH / 4) + t];
            acc.x += wv * kv.x; acc.y += wv * kv.y;
            acc.z += wv * kv.z; acc.w += wv * kv.w;
        }
    }
    *(float4*)&g_part[((size_t)cy * BB + b) * HH + t * 4] = acc;
}

__global__ void context_reduce_kernel(float* __restrict__ ctx) {
    int i = blockIdx.x * 256 + threadIdx.x;
    float s = 0.f;
#pragma unroll
    for (int j = 0; j < 32; j++) s += g_part[(size_t)j * BB * HH + i];
    ctx[i] = s;
}

// ---------------------------------------------------------------------------
extern "C" void kernel_launch(void* const* d_in, const int* in_sizes, int n_in,
                              void* d_out, int out_size) {
    const float* query = (const float*)d_in[0];
    const float* keys  = (const float*)d_in[1];
    const float* Wa_w  = (const float*)d_in[2];
    const float* Wa_b  = (const float*)d_in[3];
    const float* Ua_w  = (const float*)d_in[4];
    const float* Ua_b  = (const float*)d_in[5];
    const float* Va_w  = (const float*)d_in[6];
    // d_in[7] = Va_b: softmax shift-invariant, unused.

    float* out = (float*)d_out;
    float* out_ctx = out;            // [B,1,H]
    float* out_w = out + BB * HH;    // [B,1,S]

    __half* keys_h = nullptr;
    __half* ua_h = nullptr;
    cudaGetSymbolAddress((void**)&keys_h, g_keys_h);
    cudaGetSymbolAddress((void**)&ua_h, g_ua_h);

    cudaFuncSetAttribute(scores_kernel, cudaFuncAttributeMaxDynamicSharedMemorySize,
                         SMEM_BYTES);

    // fp16 conversions (8 floats/thread)
    cvt_kernel<<<((size_t)BB * SS * HH / 8) / 256, 256>>>(
        (const float4*)keys, (__half2*)keys_h);
    cvt_kernel<<<(HH * HH / 8) / 256, 256>>>(
        (const float4*)Ua_w, (__half2*)ua_h);

    qproj_kernel<<<BB * HH / 8, 256>>>(query, Wa_w, Wa_b, Ua_b);
    scores_kernel<<<dim3(SS / MT, BB), 512, SMEM_BYTES>>>(Va_w);
    softmax_kernel<<<BB, 256>>>(out_w);
    context_part_kernel<<<dim3(BB, 32), 256>>>(keys, out_w);
    context_reduce_kernel<<<BB * HH / 256, 256>>>(out_ctx);
}

// round 14
// speedup vs baseline: 1.1845x; 1.1845x over previous
#include <cuda_runtime.h>
#include <cuda_bf16.h>
#include <cuda_fp16.h>
#include <cstdint>

#define BB 32
#define SS 2048
#define HH 1024

// scores kernel geometry (fp16 operands)
#define MT 128              // CTA M (keys rows)
#define NTILE 256           // CTA N per pass
#define NPASS (HH / NTILE)  // 4
#define KC 64               // K halves per chunk (128B per row)
#define CPP (HH / KC)       // chunks per pass = 16
#define NCHUNKS (NPASS * CPP)  // 64
#define NSTG 4

#define STG_BYTES (16384 + 32768)   // A 16KB + B 32KB
#define A_OFF(s)  ((s) * STG_BYTES)
#define B_OFF(s)  ((s) * STG_BYTES + 16384)
#define PRE_OFF   (NSTG * STG_BYTES)
#define VA_OFF    (PRE_OFF + 4096)
#define RED_OFF   (VA_OFF + 4096)
#define SMEM_BYTES (RED_OFF + 2048)

// ---------- device scratch ----------
__device__ float g_pre[BB * HH];
__device__ float g_scores[BB * SS];
__device__ float g_part[32 * BB * HH];
__device__ __align__(16) __half g_keys_h[(size_t)BB * SS * HH];  // 128 MB
__device__ __align__(16) __half g_ua_h[HH * HH];                 // 2 MB

// ---------- helpers ----------
__device__ __forceinline__ void cp16(void* dst_smem, const void* src) {
    uint32_t d;
    asm("{ .reg .u64 t; cvta.to.shared.u64 t, %1; cvt.u32.u64 %0, t; }" : "=r"(d) : "l"(dst_smem));
    asm volatile("cp.async.cg.shared.global [%0], [%1], 16;" :: "r"(d), "l"(src) : "memory");
}
#define CP_COMMIT() asm volatile("cp.async.commit_group;" ::: "memory")
template <int N> __device__ __forceinline__ void cp_wait() {
    asm volatile("cp.async.wait_group %0;" :: "n"(N) : "memory");
}
#define LDSM_X4(r0, r1, r2, r3, addr) \
    asm volatile("ldmatrix.sync.aligned.m8n8.x4.shared.b16 {%0,%1,%2,%3}, [%4];" \
        : "=r"(r0), "=r"(r1), "=r"(r2), "=r"(r3) : "r"(addr))
#define MMA_F16(c, a, b0, b1) \
    asm volatile("mma.sync.aligned.m16n8k16.row.col.f32.f16.f16.f32 " \
        "{%0,%1,%2,%3}, {%4,%5,%6,%7}, {%8,%9}, {%0,%1,%2,%3};" \
        : "+f"((c)[0]), "+f"((c)[1]), "+f"((c)[2]), "+f"((c)[3]) \
        : "r"((a)[0]), "r"((a)[1]), "r"((a)[2]), "r"((a)[3]), "r"(b0), "r"(b1))

__device__ __forceinline__ float ftanh(float x) {
    float e = __expf(2.0f * x);
    return 1.0f - __fdividef(2.0f, e + 1.0f);
}

// ---------------------------------------------------------------------------
// K0: f32 -> fp16 conversion (8 floats / thread, vectorized)
// ---------------------------------------------------------------------------
__global__ void cvt_kernel(const float4* __restrict__ src, __half2* __restrict__ dst) {
    size_t i = (size_t)blockIdx.x * blockDim.x + threadIdx.x;
    float4 a = src[2 * i];
    float4 b = src[2 * i + 1];
    dst[4 * i + 0] = __floats2half2_rn(a.x, a.y);
    dst[4 * i + 1] = __floats2half2_rn(a.z, a.w);
    dst[4 * i + 2] = __floats2half2_rn(b.x, b.y);
    dst[4 * i + 3] = __floats2half2_rn(b.z, b.w);
}

// ---------------------------------------------------------------------------
// K1: pre[b,k] = query[b]·Wa_w[k] + Wa_b[k] + Ua_b[k]  (fp32, accuracy anchor)
// ---------------------------------------------------------------------------
__global__ void qproj_kernel(const float* __restrict__ query,
                             const float* __restrict__ Wa_w,
                             const float* __restrict__ Wa_b,
                             const float* __restrict__ Ua_b) {
    int gw = blockIdx.x * 8 + (threadIdx.x >> 5);
    int lane = threadIdx.x & 31;
    int b = gw >> 10;
    int k = gw & (HH - 1);
    const float* q = query + b * HH;
    const float* w = Wa_w + (size_t)k * HH;
    float sum = 0.f;
#pragma unroll 8
    for (int h = lane; h < HH; h += 32) sum += q[h] * w[h];
#pragma unroll
    for (int off = 16; off; off >>= 1) sum += __shfl_xor_sync(0xffffffffu, sum, off);
    if (lane == 0) g_pre[b * HH + k] = sum + Wa_b[k] + Ua_b[k];
}

// ---------------------------------------------------------------------------
// K2: fused scores via mma.sync m16n8k16 fp16 (fp32 accum).
// CTA 128(M) x 256(N) per pass, 4 passes; 8 warps as 2M x 4N, warp tile
// 64x64 (square => min fragment bytes/FLOP: 4KB/warp/k-step vs 5KB at 32x128).
// K streamed in 64-half chunks through a flat 4-stage cp.async ring.
// grid = (S/128, B) = 512, block = 256.
// ---------------------------------------------------------------------------
__global__ __launch_bounds__(256, 1) void scores_kernel(const float* __restrict__ Va_w) {
    extern __shared__ char smem[];
    float* pre_s = (float*)(smem + PRE_OFF);
    float* va_s  = (float*)(smem + VA_OFF);
    float* red   = (float*)(smem + RED_OFF);   // [4][128]

    const int tid = threadIdx.x;
    const int wid = tid >> 5;
    const int lane = tid & 31;
    const int g = lane >> 2;
    const int tg = lane & 3;
    const int wm = wid & 1;        // warp M index 0..1 (64 rows each)
    const int wn = wid >> 1;       // warp N index 0..3 (64 cols each)
    const int b = blockIdx.y;
    const int s0 = blockIdx.x * MT;

    uint32_t sb32;
    asm("{ .reg .u64 t; cvta.to.shared.u64 t, %1; cvt.u32.u64 %0, t; }"
        : "=r"(sb32) : "l"(smem));

    const char* gA = (const char*)(g_keys_h + ((size_t)b * SS + s0) * HH);

#pragma unroll
    for (int i = tid; i < HH; i += 256) {
        pre_s[i] = g_pre[b * HH + i];
        va_s[i]  = Va_w[i];
    }

    // ldmatrix lane invariants (store swizzle term = (row&7)<<4; all fragment
    // base rows are multiples of 8, so row&7 == lane&7)
    const uint32_t xr = (uint32_t)(lane & 7) << 4;
    const int a_row   = wm * 64 + ((lane >> 3) & 1) * 8 + (lane & 7);  // + mi*16
    const uint32_t a_koff = (uint32_t)(lane >> 4) * 16;
    const int b_nrow  = wn * 64 + ((lane >> 4) << 3) + (lane & 7);     // + np*16
    const uint32_t b_koff = (uint32_t)((lane >> 3) & 1) * 16;

    // chunk loader: flat chunk cl -> stage cl&3, kbyte=(cl%CPP)*128, nt=cl/CPP
    auto load_chunk = [&](int cl) {
        int st = cl & 3;
        size_t kbyte = (size_t)(cl & (CPP - 1)) * 128;
        char* Ab = smem + A_OFF(st);
        char* Bb = smem + B_OFF(st);
        const char* gBp = (const char*)(g_ua_h + ((size_t)(cl >> 4) * NTILE) * HH);
#pragma unroll
        for (int r = 0; r < 4; r++) {   // A: 128 rows x 128B
            int id = tid + 256 * r;
            int m = id >> 3, j = id & 7;
            uint32_t sw = (uint32_t)(j * 16) ^ ((uint32_t)(m & 7) << 4);
            cp16(Ab + m * 128 + sw, gA + (size_t)m * (HH * 2) + kbyte + j * 16);
        }
#pragma unroll
        for (int r = 0; r < 8; r++) {   // B: 256 rows x 128B
            int id = tid + 256 * r;
            int m = id >> 3, j = id & 7;
            uint32_t sw = (uint32_t)(j * 16) ^ ((uint32_t)(m & 7) << 4);
            cp16(Bb + m * 128 + sw, gBp + (size_t)m * (HH * 2) + kbyte + j * 16);
        }
    };

    float sacc[4][2];                  // [mi][h]: rows wm*64+mi*16+{g,g+8}
#pragma unroll
    for (int mi = 0; mi < 4; mi++) { sacc[mi][0] = 0.f; sacc[mi][1] = 0.f; }
    float acc[4][8][4];                // [mi][ni][quad]
#pragma unroll
    for (int mi = 0; mi < 4; mi++)
#pragma unroll
        for (int ni = 0; ni < 8; ni++)
#pragma unroll
            for (int q = 0; q < 4; q++) acc[mi][ni][q] = 0.f;

    load_chunk(0); CP_COMMIT();
    load_chunk(1); CP_COMMIT();
    load_chunk(2); CP_COMMIT();

    for (int cc = 0; cc < NCHUNKS; cc++) {
        cp_wait<2>();
        __syncthreads();                       // chunk cc visible; stage (cc-1)&3 free
        if (cc + 3 < NCHUNKS) load_chunk(cc + 3);
        CP_COMMIT();                           // uniform group accounting

        uint32_t Ab32 = sb32 + A_OFF(cc & 3);
        uint32_t Bb32 = sb32 + B_OFF(cc & 3);
#pragma unroll
        for (int s = 0; s < 4; s++) {          // 4 k-steps of 16 halves
            uint32_t a[4][4];
#pragma unroll
            for (int mi = 0; mi < 4; mi++) {
                uint32_t addr = Ab32 + (uint32_t)(a_row + mi * 16) * 128
                              + (((uint32_t)s * 32 + a_koff) ^ xr);
                LDSM_X4(a[mi][0], a[mi][1], a[mi][2], a[mi][3], addr);
            }
#pragma unroll
            for (int np = 0; np < 4; np++) {   // n16 tiles of this warp's 64
                uint32_t bf[4];
                uint32_t addr = Bb32 + (uint32_t)(b_nrow + np * 16) * 128
                              + (((uint32_t)s * 32 + b_koff) ^ xr);
                LDSM_X4(bf[0], bf[1], bf[2], bf[3], addr);
#pragma unroll
                for (int mi = 0; mi < 4; mi++) {
                    MMA_F16(acc[mi][np * 2],     a[mi], bf[0], bf[1]);
                    MMA_F16(acc[mi][np * 2 + 1], a[mi], bf[2], bf[3]);
                }
            }
        }

        if ((cc & (CPP - 1)) == CPP - 1) {
            // end of an n-pass: tanh + Va reduce, reset accumulators
            int nt = cc >> 4;
#pragma unroll
            for (int mi = 0; mi < 4; mi++) {
#pragma unroll
                for (int ni = 0; ni < 8; ni++) {
                    int col0 = nt * NTILE + wn * 64 + ni * 8 + tg * 2;
                    float p0 = pre_s[col0], p1 = pre_s[col0 + 1];
                    float v0 = va_s[col0],  v1 = va_s[col0 + 1];
                    sacc[mi][0] += ftanh(acc[mi][ni][0] + p0) * v0
                                 + ftanh(acc[mi][ni][1] + p1) * v1;
                    sacc[mi][1] += ftanh(acc[mi][ni][2] + p0) * v0
                                 + ftanh(acc[mi][ni][3] + p1) * v1;
                    acc[mi][ni][0] = 0.f; acc[mi][ni][1] = 0.f;
                    acc[mi][ni][2] = 0.f; acc[mi][ni][3] = 0.f;
                }
            }
        }
    }

    // quad reduce (lanes sharing a row), then across the 4 N-warps via smem
#pragma unroll
    for (int mi = 0; mi < 4; mi++)
#pragma unroll
        for (int h = 0; h < 2; h++) {
            float v = sacc[mi][h];
            v += __shfl_xor_sync(0xffffffffu, v, 1);
            v += __shfl_xor_sync(0xffffffffu, v, 2);
            if (tg == 0)
                red[wn * 128 + wm * 64 + mi * 16 + h * 8 + g] = v;
        }
    __syncthreads();
    if (tid < 128)
        g_scores[b * SS + s0 + tid] =
            red[tid] + red[128 + tid] + red[256 + tid] + red[384 + tid];
}

// ---------------------------------------------------------------------------
// K3: softmax over S per batch (Va_b dropped: shift-invariant).
// ---------------------------------------------------------------------------
__global__ void softmax_kernel(float* __restrict__ out_w) {
    int b = blockIdx.x;
    int tid = threadIdx.x;
    __shared__ float red[256];
    float v[8];
    float mx = -1e30f;
#pragma unroll
    for (int j = 0; j < 8; j++) {
        v[j] = g_scores[b * SS + tid + 256 * j];
        mx = fmaxf(mx, v[j]);
    }
    red[tid] = mx;
    __syncthreads();
    for (int off = 128; off; off >>= 1) {
        if (tid < off) red[tid] = fmaxf(red[tid], red[tid + off]);
        __syncthreads();
    }
    mx = red[0];
    __syncthreads();
    float sum = 0.f;
#pragma unroll
    for (int j = 0; j < 8; j++) {
        v[j] = __expf(v[j] - mx);
        sum += v[j];
    }
    red[tid] = sum;
    __syncthreads();
    for (int off = 128; off; off >>= 1) {
        if (tid < off) red[tid] += red[tid + off];
        __syncthreads();
    }
    float inv = 1.f / red[0];
#pragma unroll
    for (int j = 0; j < 8; j++) out_w[b * SS + tid + 256 * j] = v[j] * inv;
}

// ---------------------------------------------------------------------------
// K4a: context partials over 32 S-chunks of 64 (deterministic, f32 keys)
// ---------------------------------------------------------------------------
__global__ void context_part_kernel(const float* __restrict__ keys,
                                    const float* __restrict__ w) {
    int b = blockIdx.x;
    int cy = blockIdx.y;
    int s0 = cy * 64;
    int t = threadIdx.x;
    __shared__ float ws[64];
    if (t < 64) ws[t] = w[b * SS + s0 + t];
    __syncthreads();
    const float4* kb = (const float4*)(keys + ((size_t)b * SS + s0) * HH);
    float4 acc = {0.f, 0.f, 0.f, 0.f};
    for (int s = 0; s < 64; s += 4) {
#pragma unroll
        for (int u = 0; u < 4; u++) {
            float wv = ws[s + u];
            float4 kv = kb[(size_t)(s + u) * (HH / 4) + t];
            acc.x += wv * kv.x; acc.y += wv * kv.y;
            acc.z += wv * kv.z; acc.w += wv * kv.w;
        }
    }
    *(float4*)&g_part[((size_t)cy * BB + b) * HH + t * 4] = acc;
}

__global__ void context_reduce_kernel(float* __restrict__ ctx) {
    int i = blockIdx.x * 256 + threadIdx.x;
    float s = 0.f;
#pragma unroll
    for (int j = 0; j < 32; j++) s += g_part[(size_t)j * BB * HH + i];
    ctx[i] = s;
}

// ---------------------------------------------------------------------------
extern "C" void kernel_launch(void* const* d_in, const int* in_sizes, int n_in,
                              void* d_out, int out_size) {
    const float* query = (const float*)d_in[0];
    const float* keys  = (const float*)d_in[1];
    const float* Wa_w  = (const float*)d_in[2];
    const float* Wa_b  = (const float*)d_in[3];
    const float* Ua_w  = (const float*)d_in[4];
    const float* Ua_b  = (const float*)d_in[5];
    const float* Va_w  = (const float*)d_in[6];
    // d_in[7] = Va_b: softmax shift-invariant, unused.

    float* out = (float*)d_out;
    float* out_ctx = out;            // [B,1,H]
    float* out_w = out + BB * HH;    // [B,1,S]

    __half* keys_h = nullptr;
    __half* ua_h = nullptr;
    cudaGetSymbolAddress((void**)&keys_h, g_keys_h);
    cudaGetSymbolAddress((void**)&ua_h, g_ua_h);

    cudaFuncSetAttribute(scores_kernel, cudaFuncAttributeMaxDynamicSharedMemorySize,
                         SMEM_BYTES);

    // fp16 conversions (8 floats/thread)
    cvt_kernel<<<((size_t)BB * SS * HH / 8) / 256, 256>>>(
        (const float4*)keys, (__half2*)keys_h);
    cvt_kernel<<<(HH * HH / 8) / 256, 256>>>(
        (const float4*)Ua_w, (__half2*)ua_h);

    qproj_kernel<<<BB * HH / 8, 256>>>(query, Wa_w, Wa_b, Ua_b);
    scores_kernel<<<dim3(SS / MT, BB), 256, SMEM_BYTES>>>(Va_w);
    softmax_kernel<<<BB, 256>>>(out_w);
    context_part_kernel<<<dim3(BB, 32), 256>>>(keys, out_w);
    context_reduce_kernel<<<BB * HH / 256, 256>>>(out_ctx);
}

// round 15
// speedup vs baseline: 1.4014x; 1.1831x over previous
#include <cuda_runtime.h>
#include <cuda_bf16.h>
#include <cuda_fp16.h>
#include <cstdint>

#define BB 32
#define SS 2048
#define HH 1024

// scores kernel geometry (fp16 operands)
#define MT 128              // CTA M (keys rows)
#define NTILE 256           // CTA N per pass
#define NPASS (HH / NTILE)  // 4
#define KC 64               // K halves per chunk (128B per row)
#define CPP (HH / KC)       // chunks per pass = 16
#define NCHUNKS (NPASS * CPP)  // 64
#define NSTG 4

#define A_BYTES 16384               // 128 rows x 128B
#define B_BYTES 32768               // 256 rows x 128B
#define STG_BYTES (A_BYTES + B_BYTES)
#define A_OFF(s)  ((s) * STG_BYTES)
#define B_OFF(s)  ((s) * STG_BYTES + A_BYTES)
#define PRE_OFF   (NSTG * STG_BYTES)        // 196608
#define VA_OFF    (PRE_OFF + 4096)
#define RED_OFF   (VA_OFF + 4096)
#define MB_OFF    (RED_OFF + 2048)          // full[4] @ +0, empty[4] @ +32
#define SMEM_BYTES (MB_OFF + 128)

// ---------- device scratch ----------
__device__ float g_pre[BB * HH];
__device__ float g_scores[BB * SS];
__device__ float g_part[32 * BB * HH];
// pre-swizzled chunk-major fp16 tiles:
// keys: [512 tiles][16 kc][16384B]   ua: [4 nt][16 kc][32768B]
__device__ __align__(16) __half g_keys_h[(size_t)BB * SS * HH];  // 128 MB
__device__ __align__(16) __half g_ua_h[HH * HH];                 // 2 MB

// ---------- PTX helpers ----------
#define LDSM_X4(r0, r1, r2, r3, addr) \
    asm volatile("ldmatrix.sync.aligned.m8n8.x4.shared.b16 {%0,%1,%2,%3}, [%4];" \
        : "=r"(r0), "=r"(r1), "=r"(r2), "=r"(r3) : "r"(addr))
#define MMA_F16(c, a, b0, b1) \
    asm volatile("mma.sync.aligned.m16n8k16.row.col.f32.f16.f16.f32 " \
        "{%0,%1,%2,%3}, {%4,%5,%6,%7}, {%8,%9}, {%0,%1,%2,%3};" \
        : "+f"((c)[0]), "+f"((c)[1]), "+f"((c)[2]), "+f"((c)[3]) \
        : "r"((a)[0]), "r"((a)[1]), "r"((a)[2]), "r"((a)[3]), "r"(b0), "r"(b1))

#define MBARRIER_INIT(addr, cnt) \
    asm volatile("mbarrier.init.shared.b64 [%0], %1;" \
        :: "r"((uint32_t)(addr)), "r"((uint32_t)(cnt)) : "memory")
#define MBARRIER_ARRIVE(addr) \
    asm volatile("mbarrier.arrive.shared.b64 _, [%0];" \
        :: "r"((uint32_t)(addr)) : "memory")
#define MBARRIER_EXPECT_TX(addr, bytes) \
    asm volatile("mbarrier.arrive.expect_tx.shared.b64 _, [%0], %1;" \
        :: "r"((uint32_t)(addr)), "r"((uint32_t)(bytes)) : "memory")
#define MBARRIER_WAIT_PARITY(mbar_smem_addr, phase_parity) do { \
    uint32_t _mbar = (uint32_t)(mbar_smem_addr); \
    uint32_t _parity = (uint32_t)(phase_parity); \
    uint32_t _done; \
    asm volatile("{\n\t.reg .pred p;\n\t" \
        "mbarrier.try_wait.parity.acquire.cta.shared::cta.b64 p, [%1], %2;\n\t" \
        "selp.b32 %0, 1, 0, p;\n\t}" : "=r"(_done) : "r"(_mbar), "r"(_parity) : "memory"); \
    if (!_done) { \
        asm volatile("{\n\t.reg .pred P1;\n\t" \
            "WAIT_LOOP_%=:\n\t" \
            "mbarrier.try_wait.parity.acquire.cta.shared::cta.b64 P1, [%0], %1, 0x989680;\n\t" \
            "@P1 bra.uni WAIT_DONE_%=;\n\t" \
            "bra.uni WAIT_LOOP_%=;\n\t" \
            "WAIT_DONE_%=:\n\t}" :: "r"(_mbar), "r"(_parity) : "memory"); \
    } \
} while(0)

__device__ __forceinline__ void bulk_g2s(uint32_t dst_smem, const void* src,
                                         uint32_t bytes, uint32_t mbar) {
    asm volatile(
        "cp.async.bulk.shared::cluster.global.mbarrier::complete_tx::bytes "
        "[%0], [%1], %2, [%3];"
        :: "r"(dst_smem), "l"(src), "r"(bytes), "r"(mbar) : "memory");
}

__device__ __forceinline__ float ftanh(float x) {
    float e = __expf(2.0f * x);
    return 1.0f - __fdividef(2.0f, e + 1.0f);
}

// ---------------------------------------------------------------------------
// K0a: keys f32 -> fp16, chunk-major pre-swizzled layout.
// thread -> 8 consecutive h of one (row, kc). 8M threads.
// ---------------------------------------------------------------------------
__global__ void cvt_keys_kernel(const float4* __restrict__ src, char* __restrict__ dst) {
    int idx = blockIdx.x * 256 + threadIdx.x;
    int sg = idx >> 7;               // global row (b*SS+s), 0..65535
    int hi = (idx & 127) << 3;       // h start
    float4 a = src[(size_t)idx * 2];
    float4 b = src[(size_t)idx * 2 + 1];
    uint4 p;
    ((__half2*)&p)[0] = __floats2half2_rn(a.x, a.y);
    ((__half2*)&p)[1] = __floats2half2_rn(a.z, a.w);
    ((__half2*)&p)[2] = __floats2half2_rn(b.x, b.y);
    ((__half2*)&p)[3] = __floats2half2_rn(b.z, b.w);
    int tile = sg >> 7, row = sg & 127, kc = hi >> 6, col = hi & 63;
    size_t off = ((size_t)(tile * 16 + kc) << 14)
               + (uint32_t)row * 128
               + (((uint32_t)col * 2) ^ (((uint32_t)row & 7) << 4));
    *(uint4*)(dst + off) = p;
}

// K0b: Ua f32 -> fp16, chunk-major pre-swizzled (256-row tiles). 128K threads.
__global__ void cvt_ua_kernel(const float4* __restrict__ src, char* __restrict__ dst) {
    int idx = blockIdx.x * 256 + threadIdx.x;
    int n = idx >> 7;                // Ua row 0..1023
    int hi = (idx & 127) << 3;
    float4 a = src[(size_t)idx * 2];
    float4 b = src[(size_t)idx * 2 + 1];
    uint4 p;
    ((__half2*)&p)[0] = __floats2half2_rn(a.x, a.y);
    ((__half2*)&p)[1] = __floats2half2_rn(a.z, a.w);
    ((__half2*)&p)[2] = __floats2half2_rn(b.x, b.y);
    ((__half2*)&p)[3] = __floats2half2_rn(b.z, b.w);
    int nt = n >> 8, row = n & 255, kc = hi >> 6, col = hi & 63;
    size_t off = ((size_t)(nt * 16 + kc) << 15)
               + (uint32_t)row * 128
               + (((uint32_t)col * 2) ^ (((uint32_t)row & 7) << 4));
    *(uint4*)(dst + off) = p;
}

// ---------------------------------------------------------------------------
// K1: pre[b,k] = query[b]·Wa_w[k] + Wa_b[k] + Ua_b[k]  (fp32, accuracy anchor)
// ---------------------------------------------------------------------------
__global__ void qproj_kernel(const float* __restrict__ query,
                             const float* __restrict__ Wa_w,
                             const float* __restrict__ Wa_b,
                             const float* __restrict__ Ua_b) {
    int gw = blockIdx.x * 8 + (threadIdx.x >> 5);
    int lane = threadIdx.x & 31;
    int b = gw >> 10;
    int k = gw & (HH - 1);
    const float* q = query + b * HH;
    const float* w = Wa_w + (size_t)k * HH;
    float sum = 0.f;
#pragma unroll 8
    for (int h = lane; h < HH; h += 32) sum += q[h] * w[h];
#pragma unroll
    for (int off = 16; off; off >>= 1) sum += __shfl_xor_sync(0xffffffffu, sum, off);
    if (lane == 0) g_pre[b * HH + k] = sum + Wa_b[k] + Ua_b[k];
}

// ---------------------------------------------------------------------------
// K2: fused scores, mma.sync m16n8k16 fp16 / f32 accum.
// CTA 128x256 per pass, 4 passes; 8 warps (2M x 4N), warp tile 64x64.
// K streamed in 64-half chunks: cp.async.bulk (1 producer thread) through a
// 4-stage mbarrier full/empty ring — no per-chunk __syncthreads, no LDGSTS.
// grid = (S/128, B) = 512, block = 256.
// ---------------------------------------------------------------------------
__global__ __launch_bounds__(256, 1) void scores_kernel(const float* __restrict__ Va_w) {
    extern __shared__ char smem[];
    float* pre_s = (float*)(smem + PRE_OFF);
    float* va_s  = (float*)(smem + VA_OFF);
    float* red   = (float*)(smem + RED_OFF);   // [4][128]

    const int tid = threadIdx.x;
    const int wid = tid >> 5;
    const int lane = tid & 31;
    const int g = lane >> 2;
    const int tg = lane & 3;
    const int wm = wid & 1;        // warp M index (64 rows each)
    const int wn = wid >> 1;       // warp N index 0..3 (64 cols each)
    const int b = blockIdx.y;
    const int s0 = blockIdx.x * MT;

    uint32_t sb32;
    asm("{ .reg .u64 t; cvta.to.shared.u64 t, %1; cvt.u32.u64 %0, t; }"
        : "=r"(sb32) : "l"(smem));
    const uint32_t fullb  = sb32 + MB_OFF;        // + 8*st
    const uint32_t emptyb = sb32 + MB_OFF + 32;   // + 8*st

    const char* keys_c = (const char*)g_keys_h;
    const char* ua_c   = (const char*)g_ua_h;
    const int tI = b * (SS / MT) + blockIdx.x;    // tile index for A

    if (tid == 0) {
#pragma unroll
        for (int s = 0; s < NSTG; s++) {
            MBARRIER_INIT(fullb + 8 * s, 1);
            MBARRIER_INIT(emptyb + 8 * s, 256);
        }
        asm volatile("fence.proxy.async.shared::cta;" ::: "memory");
    }
#pragma unroll
    for (int i = tid; i < HH; i += 256) {
        pre_s[i] = g_pre[b * HH + i];
        va_s[i]  = Va_w[i];
    }
    __syncthreads();

    // producer chunk issue (thread 0)
    auto issue_chunk = [&](int cl) {
        int st = cl & 3;
        MBARRIER_EXPECT_TX(fullb + 8 * st, A_BYTES + B_BYTES);
        const char* srcA = keys_c + ((size_t)(tI * 16 + (cl & 15)) << 14);
        const char* srcB = ua_c + ((size_t)((cl >> 4) * 16 + (cl & 15)) << 15);
        bulk_g2s(sb32 + A_OFF(st), srcA, A_BYTES, fullb + 8 * st);
        bulk_g2s(sb32 + B_OFF(st), srcB, B_BYTES, fullb + 8 * st);
    };

    if (tid == 0) { issue_chunk(0); issue_chunk(1); issue_chunk(2); }

    // ldmatrix lane invariants (base rows are multiples of 8 => row&7 == lane&7)
    const uint32_t xr = (uint32_t)(lane & 7) << 4;
    const int a_row   = wm * 64 + ((lane >> 3) & 1) * 8 + (lane & 7);  // + mi*16
    const uint32_t a_koff = (uint32_t)(lane >> 4) * 16;
    const int b_nrow  = wn * 64 + ((lane >> 4) << 3) + (lane & 7);     // + np*16
    const uint32_t b_koff = (uint32_t)((lane >> 3) & 1) * 16;

    float sacc[4][2];
#pragma unroll
    for (int mi = 0; mi < 4; mi++) { sacc[mi][0] = 0.f; sacc[mi][1] = 0.f; }
    float acc[4][8][4];
#pragma unroll
    for (int mi = 0; mi < 4; mi++)
#pragma unroll
        for (int ni = 0; ni < 8; ni++)
#pragma unroll
            for (int q = 0; q < 4; q++) acc[mi][ni][q] = 0.f;

    uint32_t full_ph = 0, empty_ph = 0;   // per-stage phase bits

    for (int cc = 0; cc < NCHUNKS; cc++) {
        const int st = cc & 3;
        // producer: refill stage (cc+3)&3 once its consumers have drained
        if (tid == 0 && cc + 3 < NCHUNKS) {
            int pst = (cc + 3) & 3;
            if (cc + 3 >= NSTG) {
                MBARRIER_WAIT_PARITY(emptyb + 8 * pst, (empty_ph >> pst) & 1u);
                empty_ph ^= 1u << pst;
            }
            issue_chunk(cc + 3);
        }
        // consumer: wait chunk cc data
        MBARRIER_WAIT_PARITY(fullb + 8 * st, (full_ph >> st) & 1u);
        full_ph ^= 1u << st;

        uint32_t Ab32 = sb32 + A_OFF(st);
        uint32_t Bb32 = sb32 + B_OFF(st);
#pragma unroll
        for (int s = 0; s < 4; s++) {          // 4 k-steps of 16 halves
            uint32_t a[4][4];
#pragma unroll
            for (int mi = 0; mi < 4; mi++) {
                uint32_t addr = Ab32 + (uint32_t)(a_row + mi * 16) * 128
                              + (((uint32_t)s * 32 + a_koff) ^ xr);
                LDSM_X4(a[mi][0], a[mi][1], a[mi][2], a[mi][3], addr);
            }
#pragma unroll
            for (int np = 0; np < 4; np++) {
                uint32_t bf[4];
                uint32_t addr = Bb32 + (uint32_t)(b_nrow + np * 16) * 128
                              + (((uint32_t)s * 32 + b_koff) ^ xr);
                LDSM_X4(bf[0], bf[1], bf[2], bf[3], addr);
#pragma unroll
                for (int mi = 0; mi < 4; mi++) {
                    MMA_F16(acc[mi][np * 2],     a[mi], bf[0], bf[1]);
                    MMA_F16(acc[mi][np * 2 + 1], a[mi], bf[2], bf[3]);
                }
            }
        }
        MBARRIER_ARRIVE(emptyb + 8 * st);      // this thread done with stage st

        if ((cc & (CPP - 1)) == CPP - 1) {
            // end of an n-pass: tanh + Va reduce, reset accumulators
            int nt = cc >> 4;
#pragma unroll
            for (int mi = 0; mi < 4; mi++) {
#pragma unroll
                for (int ni = 0; ni < 8; ni++) {
                    int col0 = nt * NTILE + wn * 64 + ni * 8 + tg * 2;
                    float p0 = pre_s[col0], p1 = pre_s[col0 + 1];
                    float v0 = va_s[col0],  v1 = va_s[col0 + 1];
                    sacc[mi][0] += ftanh(acc[mi][ni][0] + p0) * v0
                                 + ftanh(acc[mi][ni][1] + p1) * v1;
                    sacc[mi][1] += ftanh(acc[mi][ni][2] + p0) * v0
                                 + ftanh(acc[mi][ni][3] + p1) * v1;
                    acc[mi][ni][0] = 0.f; acc[mi][ni][1] = 0.f;
                    acc[mi][ni][2] = 0.f; acc[mi][ni][3] = 0.f;
                }
            }
        }
    }

    // quad reduce, then across the 4 N-warps via smem
#pragma unroll
    for (int mi = 0; mi < 4; mi++)
#pragma unroll
        for (int h = 0; h < 2; h++) {
            float v = sacc[mi][h];
            v += __shfl_xor_sync(0xffffffffu, v, 1);
            v += __shfl_xor_sync(0xffffffffu, v, 2);
            if (tg == 0)
                red[wn * 128 + wm * 64 + mi * 16 + h * 8 + g] = v;
        }
    __syncthreads();
    if (tid < 128)
        g_scores[b * SS + s0 + tid] =
            red[tid] + red[128 + tid] + red[256 + tid] + red[384 + tid];
}

// ---------------------------------------------------------------------------
// K3: softmax over S per batch (Va_b dropped: shift-invariant).
// ---------------------------------------------------------------------------
__global__ void softmax_kernel(float* __restrict__ out_w) {
    int b = blockIdx.x;
    int tid = threadIdx.x;
    __shared__ float red[256];
    float v[8];
    float mx = -1e30f;
#pragma unroll
    for (int j = 0; j < 8; j++) {
        v[j] = g_scores[b * SS + tid + 256 * j];
        mx = fmaxf(mx, v[j]);
    }
    red[tid] = mx;
    __syncthreads();
    for (int off = 128; off; off >>= 1) {
        if (tid < off) red[tid] = fmaxf(red[tid], red[tid + off]);
        __syncthreads();
    }
    mx = red[0];
    __syncthreads();
    float sum = 0.f;
#pragma unroll
    for (int j = 0; j < 8; j++) {
        v[j] = __expf(v[j] - mx);
        sum += v[j];
    }
    red[tid] = sum;
    __syncthreads();
    for (int off = 128; off; off >>= 1) {
        if (tid < off) red[tid] += red[tid + off];
        __syncthreads();
    }
    float inv = 1.f / red[0];
#pragma unroll
    for (int j = 0; j < 8; j++) out_w[b * SS + tid + 256 * j] = v[j] * inv;
}

// ---------------------------------------------------------------------------
// K4a: context partials over 32 S-chunks of 64 (deterministic, f32 keys)
// ---------------------------------------------------------------------------
__global__ void context_part_kernel(const float* __restrict__ keys,
                                    const float* __restrict__ w) {
    int b = blockIdx.x;
    int cy = blockIdx.y;
    int s0 = cy * 64;
    int t = threadIdx.x;
    __shared__ float ws[64];
    if (t < 64) ws[t] = w[b * SS + s0 + t];
    __syncthreads();
    const float4* kb = (const float4*)(keys + ((size_t)b * SS + s0) * HH);
    float4 acc = {0.f, 0.f, 0.f, 0.f};
    for (int s = 0; s < 64; s += 4) {
#pragma unroll
        for (int u = 0; u < 4; u++) {
            float wv = ws[s + u];
            float4 kv = kb[(size_t)(s + u) * (HH / 4) + t];
            acc.x += wv * kv.x; acc.y += wv * kv.y;
            acc.z += wv * kv.z; acc.w += wv * kv.w;
        }
    }
    *(float4*)&g_part[((size_t)cy * BB + b) * HH + t * 4] = acc;
}

__global__ void context_reduce_kernel(float* __restrict__ ctx) {
    int i = blockIdx.x * 256 + threadIdx.x;
    float s = 0.f;
#pragma unroll
    for (int j = 0; j < 32; j++) s += g_part[(size_t)j * BB * HH + i];
    ctx[i] = s;
}

// ---------------------------------------------------------------------------
extern "C" void kernel_launch(void* const* d_in, const int* in_sizes, int n_in,
                              void* d_out, int out_size) {
    const float* query = (const float*)d_in[0];
    const float* keys  = (const float*)d_in[1];
    const float* Wa_w  = (const float*)d_in[2];
    const float* Wa_b  = (const float*)d_in[3];
    const float* Ua_w  = (const float*)d_in[4];
    const float* Ua_b  = (const float*)d_in[5];
    const float* Va_w  = (const float*)d_in[6];
    // d_in[7] = Va_b: softmax shift-invariant, unused.

    float* out = (float*)d_out;
    float* out_ctx = out;            // [B,1,H]
    float* out_w = out + BB * HH;    // [B,1,S]

    char* keys_c = nullptr;
    char* ua_c = nullptr;
    cudaGetSymbolAddress((void**)&keys_c, g_keys_h);
    cudaGetSymbolAddress((void**)&ua_c, g_ua_h);

    cudaFuncSetAttribute(scores_kernel, cudaFuncAttributeMaxDynamicSharedMemorySize,
                         SMEM_BYTES);

    cvt_keys_kernel<<<((size_t)BB * SS * HH / 8) / 256, 256>>>(
        (const float4*)keys, keys_c);
    cvt_ua_kernel<<<(HH * HH / 8) / 256, 256>>>(
        (const float4*)Ua_w, ua_c);

    qproj_kernel<<<BB * HH / 8, 256>>>(query, Wa_w, Wa_b, Ua_b);
    scores_kernel<<<dim3(SS / MT, BB), 256, SMEM_BYTES>>>(Va_w);
    softmax_kernel<<<BB, 256>>>(out_w);
    context_part_kernel<<<dim3(BB, 32), 256>>>(keys, out_w);
    context_reduce_kernel<<<BB * HH / 256, 256>>>(out_ctx);
}